// round 14
// baseline (speedup 1.0000x reference)
#include <cuda_runtime.h>
#include <cuda_bf16.h>
#include <cstdint>

#define M_TOT   131072
#define N_EMB   1024
#define K_DIM   256
#define HW      4096
#define Z_ELEMS 33554432
#define GATHER_BLOCKS 4096
#define WINF    2.5e-3f

typedef unsigned long long u64;

__device__ float g_t[N_EMB];
__device__ float g_s[M_TOT];
__device__ float g_part[GATHER_BLOCKS];
__device__ __nv_bfloat16 g_A[(size_t)M_TOT * K_DIM];     // bf16(z), [m][k]
__device__ __nv_bfloat16 g_B[(size_t)N_EMB * K_DIM];     // bf16(emb), [n][k]
__device__ unsigned short g_cand[(size_t)M_TOT * 64];    // per pixel: 2 halves x [cnt, c0..c30]

#define SW128(o) ((o) ^ (((o) >> 3) & 0x70))

__device__ __forceinline__ uint32_t smem_u32(const void* p) {
    uint32_t a;
    asm("{ .reg .u64 t; cvta.to.shared.u64 t, %1; cvt.u32.u64 %0, t; }" : "=r"(a) : "l"(p));
    return a;
}
__device__ __forceinline__ unsigned fkey(float f) {
    unsigned b = __float_as_uint(f);
    return (b & 0x80000000u) ? ~b : (b | 0x80000000u);
}
__device__ __forceinline__ float fdecode(unsigned k) {
    unsigned b = (k & 0x80000000u) ? (k ^ 0x80000000u) : ~k;
    return __uint_as_float(b);
}

#define LDSM_X4(r0, r1, r2, r3, addr) \
    asm volatile("ldmatrix.sync.aligned.m8n8.x4.shared.b16 {%0,%1,%2,%3}, [%4];" \
        : "=r"(r0), "=r"(r1), "=r"(r2), "=r"(r3) : "r"(addr))

#define MMA16816(d, a, b0, b1) \
    asm volatile("mma.sync.aligned.m16n8k16.row.col.f32.bf16.bf16.f32 " \
        "{%0,%1,%2,%3}, {%4,%5,%6,%7}, {%8,%9}, {%0,%1,%2,%3};" \
        : "+f"((d)[0]), "+f"((d)[1]), "+f"((d)[2]), "+f"((d)[3]) \
        : "r"((a)[0]), "r"((a)[1]), "r"((a)[2]), "r"((a)[3]), "r"(b0), "r"(b1))

#define CP_ASYNC16(dst, src) \
    asm volatile("cp.async.cg.shared.global [%0], [%1], 16;" :: "r"(dst), "l"(src))
#define CP_COMMIT() asm volatile("cp.async.commit_group;")
#define CP_WAIT0()  asm volatile("cp.async.wait_group 0;")

// ===================== kernel A: fused split (z + emb -> bf16) ===========
__global__ __launch_bounds__(256) void k_split(const float* __restrict__ z,
                                               const float* __restrict__ emb) {
    const int tid = threadIdx.x;
    if (blockIdx.x >= 4096) {
        int n = (blockIdx.x - 4096) * 256 + tid;
        const float4* er = reinterpret_cast<const float4*>(emb + (size_t)n * K_DIM);
        #pragma unroll 4
        for (int c8 = 0; c8 < 32; ++c8) {
            float4 v0 = er[c8 * 2], v1 = er[c8 * 2 + 1];
            __nv_bfloat16 h[8] = {
                __float2bfloat16_rn(v0.x), __float2bfloat16_rn(v0.y),
                __float2bfloat16_rn(v0.z), __float2bfloat16_rn(v0.w),
                __float2bfloat16_rn(v1.x), __float2bfloat16_rn(v1.y),
                __float2bfloat16_rn(v1.z), __float2bfloat16_rn(v1.w) };
            *reinterpret_cast<uint4*>(&g_B[(size_t)n * K_DIM + c8 * 8]) =
                *reinterpret_cast<uint4*>(h);
        }
        return;
    }
    __shared__ float zs[256][33];
    const int m0 = blockIdx.x * 32, b = m0 / HW, hw0 = m0 & (HW - 1);
    #pragma unroll
    for (int it = 0; it < 8; ++it) {                 // float4 global loads
        int f = it * 256 + tid;
        int c = f >> 3, r4 = (f & 7) * 4;
        float4 v = *reinterpret_cast<const float4*>(
            z + ((size_t)b * K_DIM + c) * HW + hw0 + r4);
        zs[c][r4] = v.x; zs[c][r4 + 1] = v.y;
        zs[c][r4 + 2] = v.z; zs[c][r4 + 3] = v.w;
    }
    __syncthreads();
    for (int i = tid; i < 1024; i += 256) {
        int r = i >> 5, c8 = (i & 31) * 8;
        __nv_bfloat16 h[8];
        #pragma unroll
        for (int j = 0; j < 8; ++j) h[j] = __float2bfloat16_rn(zs[c8 + j][r]);
        *reinterpret_cast<uint4*>(&g_A[(size_t)(m0 + r) * K_DIM + c8]) =
            *reinterpret_cast<uint4*>(h);
    }
    if (tid < 32) {
        float s = 0.f;
        #pragma unroll 8
        for (int c = 0; c < K_DIM; ++c) { float v = zs[c][tid]; s = fmaf(v, v, s); }
        g_s[m0 + tid] = s;
    }
}

// ===================== kernel B: emb norms (sequential-k, exact) =========
__global__ void k_embnorm(const float* __restrict__ emb) {
    int n = blockIdx.x * blockDim.x + threadIdx.x;
    if (n < N_EMB) {
        const float* e = emb + (size_t)n * K_DIM;
        float s = 0.f;
        #pragma unroll 8
        for (int c = 0; c < K_DIM; ++c) s = fmaf(e[c], e[c], s);
        g_t[n] = s;
    }
}

// ===================== kernel C: fused GEMM + argmin candidates ==========
// Grid 2048 = 1024 m-tiles x 2 n-halves (512 cols each). Warp grid 4(m)x2(n),
// warp tile 32x64 (R7 shape). A resident 64KB; B double-buffered.
// Per-half candidate lists are independently safe (winner beats its own
// half's min by < WINF); select merges + rescores exactly.
// smem: A 65536 | B 2x16384 | Ts 4096 | tminU 2048 | bmp 8192 = 112640 B
__global__ __launch_bounds__(256, 2) void k_gemm() {
    extern __shared__ __align__(16) unsigned char smem[];
    const uint32_t sbase = smem_u32(smem);
    const uint32_t SA = 0, SB = 65536, STS = 98304, STM = 102400, SBM = 104448;
    float*    Ts    = reinterpret_cast<float*>(smem + STS);
    unsigned* tminU = reinterpret_cast<unsigned*>(smem + STM);
    unsigned* bmp   = reinterpret_cast<unsigned*>(smem + SBM);

    const int tid = threadIdx.x, wid = tid >> 5, lane = tid & 31;
    const int m0 = (blockIdx.x >> 1) * 128;
    const int half = blockIdx.x & 1;
    const int nbase = half * 512;
    const int mw = wid >> 1, nw = wid & 1;
    const int g = lane >> 2, t = lane & 3;
    const int li = lane & 7, ls = lane >> 3;

    const unsigned char* gAb = reinterpret_cast<const unsigned char*>(g_A);
    const unsigned char* gBb = reinterpret_cast<const unsigned char*>(g_B);
    const int r  = tid >> 3;
    const int cb = (tid & 7) * 16;

    for (int i = tid; i < N_EMB; i += 256) Ts[i] = g_t[i];
    for (int i = tid; i < 512; i += 256) tminU[i] = 0xFFFFFFFFu;
    for (int i = tid; i < 2048; i += 256) bmp[i] = 0u;

    #pragma unroll
    for (int kc = 0; kc < 4; ++kc)
        #pragma unroll
        for (int i = 0; i < 4; ++i) {
            int f = tid + i * 256;
            int rr = f >> 3, cc = (f & 7) * 16;
            CP_ASYNC16(sbase + SA + kc * 16384u + SW128(rr * 128 + cc),
                       gAb + (size_t)(m0 + rr) * 512 + kc * 128 + cc);
        }
    #pragma unroll
    for (int i = 0; i < 4; ++i) {
        int rr = r + i * 32;
        CP_ASYNC16(sbase + SB + SW128(rr * 128 + cb),
                   gBb + (size_t)(nbase + rr) * 512 + cb);
    }
    CP_COMMIT();

    float d[2][8][4];
    #pragma unroll
    for (int i = 0; i < 2; ++i)
        #pragma unroll
        for (int j = 0; j < 8; ++j)
            #pragma unroll
            for (int q = 0; q < 4; ++q) d[i][j][q] = 0.f;

    uint32_t buf = 0;
    for (int nc = 0; nc < 4; ++nc) {
        for (int kc = 0; kc < 4; ++kc) {
            CP_WAIT0();
            __syncthreads();
            int nn = nc, nk = kc + 1;
            if (nk == 4) { nk = 0; ++nn; }
            if (nn < 4) {
                uint32_t nb = buf ^ 1;
                #pragma unroll
                for (int i = 0; i < 4; ++i) {
                    int rr = r + i * 32;
                    CP_ASYNC16(sbase + SB + nb * 16384u + SW128(rr * 128 + cb),
                               gBb + (size_t)(nbase + nn * 128 + rr) * 512 + nk * 128 + cb);
                }
                CP_COMMIT();
            }
            const uint32_t sAu = sbase + SA + kc * 16384u;
            const uint32_t sBu = sbase + SB + buf * 16384u;
            #pragma unroll
            for (int ks = 0; ks < 4; ++ks) {
                uint32_t a[2][4];
                #pragma unroll
                for (int mb = 0; mb < 2; ++mb) {
                    int row = mw * 32 + mb * 16 + li + (ls & 1) * 8;
                    int boff = ks * 32 + (ls >> 1) * 16;
                    LDSM_X4(a[mb][0], a[mb][1], a[mb][2], a[mb][3],
                            sAu + SW128(row * 128 + boff));
                }
                #pragma unroll
                for (int nbp = 0; nbp < 4; ++nbp) {
                    uint32_t bf[4];
                    int row = nw * 64 + nbp * 16 + li + (ls >> 1) * 8;
                    int boff = ks * 32 + (ls & 1) * 16;
                    LDSM_X4(bf[0], bf[1], bf[2], bf[3],
                            sBu + SW128(row * 128 + boff));
                    #pragma unroll
                    for (int mb = 0; mb < 2; ++mb) {
                        MMA16816(d[mb][nbp * 2],     a[mb], bf[0], bf[1]);
                        MMA16816(d[mb][nbp * 2 + 1], a[mb], bf[2], bf[3]);
                    }
                }
            }
            buf ^= 1;
        }
        // ---- barrier-free epilogue for n-chunk nc (tight threshold) ----
        float rowmin[4];                   // j = mb*2 + h
        #pragma unroll
        for (int mb = 0; mb < 2; ++mb) {
            float mn0 = 3.4e38f, mn1 = 3.4e38f;
            #pragma unroll
            for (int nb = 0; nb < 8; ++nb) {
                int cg = nbase + nc * 128 + nw * 64 + nb * 8 + t * 2;
                float t0 = Ts[cg], t1 = Ts[cg + 1];
                float u0 = fmaf(-2.f, d[mb][nb][0], t0);
                float u1 = fmaf(-2.f, d[mb][nb][1], t1);
                float u2 = fmaf(-2.f, d[mb][nb][2], t0);
                float u3 = fmaf(-2.f, d[mb][nb][3], t1);
                d[mb][nb][0] = u0; d[mb][nb][1] = u1;
                d[mb][nb][2] = u2; d[mb][nb][3] = u3;
                mn0 = fminf(mn0, fminf(u0, u1));
                mn1 = fminf(mn1, fminf(u2, u3));
            }
            rowmin[mb * 2] = mn0; rowmin[mb * 2 + 1] = mn1;
        }
        #pragma unroll
        for (int j = 0; j < 4; ++j) {
            rowmin[j] = fminf(rowmin[j], __shfl_xor_sync(0xffffffffu, rowmin[j], 1));
            rowmin[j] = fminf(rowmin[j], __shfl_xor_sync(0xffffffffu, rowmin[j], 2));
        }
        unsigned tk[4];
        #pragma unroll
        for (int j = 0; j < 4; ++j) tk[j] = fkey(rowmin[j]);
        if (t == 0) {
            #pragma unroll
            for (int j = 0; j < 4; ++j) {
                int row = mw * 32 + (j >> 1) * 16 + (j & 1) * 8 + g;
                unsigned old = atomicMin(&tminU[row * 4 + nc], tk[j]);
                tk[j] = (old < tk[j]) ? old : tk[j];
            }
        }
        #pragma unroll
        for (int j = 0; j < 4; ++j)
            tk[j] = __shfl_sync(0xffffffffu, tk[j], lane & ~3);
        #pragma unroll
        for (int mb = 0; mb < 2; ++mb) {
            #pragma unroll
            for (int h = 0; h < 2; ++h) {
                int row = mw * 32 + mb * 16 + h * 8 + g;
                float thr = fdecode(tk[mb * 2 + h]) + WINF;
                #pragma unroll
                for (int nb = 0; nb < 8; ++nb) {
                    int col = nw * 64 + nb * 8 + t * 2;
                    float u0 = d[mb][nb][h * 2];
                    float u1 = d[mb][nb][h * 2 + 1];
                    if (u0 < thr)
                        atomicOr(&bmp[(row * 4 + nc) * 4 + (col >> 5)], 1u << (col & 31));
                    if (u1 < thr)
                        atomicOr(&bmp[(row * 4 + nc) * 4 + ((col + 1) >> 5)], 1u << ((col + 1) & 31));
                }
            }
        }
        #pragma unroll
        for (int i = 0; i < 2; ++i)
            #pragma unroll
            for (int j = 0; j < 8; ++j)
                #pragma unroll
                for (int q = 0; q < 4; ++q) d[i][j][q] = 0.f;
    }
    __syncthreads();

    // ---- end phase: per-half prune + candidate list (cap 31) ----
    if (tid < 128) {
        int row = tid, m = m0 + row;
        float tm[4], gmin = 3.4e38f;
        #pragma unroll
        for (int nc = 0; nc < 4; ++nc) {
            tm[nc] = fdecode(tminU[row * 4 + nc]);
            gmin = fminf(gmin, tm[nc]);
        }
        float thr = gmin + WINF;
        unsigned short* cd = g_cand + (size_t)m * 64 + half * 32;
        int cnt = 0;
        #pragma unroll
        for (int nc = 0; nc < 4; ++nc) {
            if (tm[nc] <= thr) {
                #pragma unroll
                for (int w = 0; w < 4; ++w) {
                    unsigned bits = bmp[(row * 4 + nc) * 4 + w];
                    while (bits) {
                        int bb = __ffs(bits) - 1;
                        bits &= bits - 1;
                        if (cnt < 31)
                            cd[1 + cnt] = (unsigned short)(nbase + nc * 128 + w * 32 + bb);
                        ++cnt;
                    }
                }
            }
        }
        cd[0] = (cnt <= 31) ? (unsigned short)cnt : (unsigned short)0xFFFF;
    }
}

// ===================== kernel D: rescore + gather + loss =================
__global__ __launch_bounds__(256) void k_select(const float* __restrict__ z,
                                                const float* __restrict__ emb,
                                                float* __restrict__ out) {
    extern __shared__ __align__(16) unsigned char dsm[];
    float (*zs)[33]  = reinterpret_cast<float(*)[33]>(dsm);             // 33792
    u64*   keys      = reinterpret_cast<u64*>(dsm + 33792);             // 256
    unsigned* pairs  = reinterpret_cast<unsigned*>(dsm + 34048);        // 8064
    int*   offs      = reinterpret_cast<int*>(dsm + 42112);             // 136
    unsigned* ovfm   = reinterpret_cast<unsigned*>(dsm + 42248);        // 4
    float (*sm)[257] = reinterpret_cast<float(*)[257]>(dsm + 33792);    // reuse (phase2)
    int*   sidx      = reinterpret_cast<int*>(dsm + 66688);             // 128
    float* red       = reinterpret_cast<float*>(dsm + 66816);           // 1024 -> 67840

    const int tid = threadIdx.x, wid = tid >> 5, lane = tid & 31;
    const int m0 = blockIdx.x * 32, b = m0 / HW, hw0 = m0 & (HW - 1);

    #pragma unroll
    for (int it = 0; it < 8; ++it) {                 // float4 global loads
        int f = it * 256 + tid;
        int c = f >> 3, r4 = (f & 7) * 4;
        float4 v = *reinterpret_cast<const float4*>(
            z + ((size_t)b * K_DIM + c) * HW + hw0 + r4);
        zs[c][r4] = v.x; zs[c][r4 + 1] = v.y;
        zs[c][r4 + 2] = v.z; zs[c][r4 + 3] = v.w;
    }
    if (wid == 0) {
        unsigned short c0 = g_cand[(size_t)(m0 + lane) * 64];
        unsigned short c1 = g_cand[(size_t)(m0 + lane) * 64 + 32];
        bool ovf = (c0 == 0xFFFFu) || (c1 == 0xFFFFu);
        unsigned obal = __ballot_sync(0xffffffffu, ovf);
        int cnt = ovf ? 0 : (int)c0 + (int)c1;
        int ex = cnt;
        #pragma unroll
        for (int o = 1; o < 32; o <<= 1) {
            int v = __shfl_up_sync(0xffffffffu, ex, o);
            if (lane >= o) ex += v;
        }
        offs[lane + 1] = ex;
        if (lane == 0) { offs[0] = 0; *ovfm = obal; }
        keys[lane] = ~0ull;
    }
    __syncthreads();
    if (tid < 32) {
        unsigned short c0 = g_cand[(size_t)(m0 + tid) * 64];
        unsigned short c1 = g_cand[(size_t)(m0 + tid) * 64 + 32];
        if (c0 != 0xFFFFu && c1 != 0xFFFFu) {
            int off = offs[tid];
            for (int j = 0; j < (int)c0; ++j)
                pairs[off++] = ((unsigned)tid << 16) |
                               (unsigned)g_cand[(size_t)(m0 + tid) * 64 + 1 + j];
            for (int j = 0; j < (int)c1; ++j)
                pairs[off++] = ((unsigned)tid << 16) |
                               (unsigned)g_cand[(size_t)(m0 + tid) * 64 + 33 + j];
        }
    }
    __syncthreads();

    const int T = offs[32];
    for (int i = tid; i < T; i += 256) {
        unsigned pr = pairs[i];
        int p = pr >> 16, n = pr & 0xFFFF;
        const float4* e4 = reinterpret_cast<const float4*>(emb + (size_t)n * K_DIM);
        float acc = 0.f;
        #pragma unroll 8
        for (int k4 = 0; k4 < 64; ++k4) {
            float4 v = e4[k4];
            int k = k4 * 4;
            acc = fmaf(zs[k][p], v.x, acc);
            acc = fmaf(zs[k + 1][p], v.y, acc);
            acc = fmaf(zs[k + 2][p], v.z, acc);
            acc = fmaf(zs[k + 3][p], v.w, acc);
        }
        float dd = fmaf(-2.f, acc, g_s[m0 + p] + g_t[n]);
        atomicMin(&keys[p], ((u64)fkey(dd) << 32) | (unsigned)n);
    }
    {
        unsigned obal = *ovfm;
        if (obal) {
            for (int p = wid; p < 32; p += 8) {
                if ((obal >> p) & 1u) {
                    const float s = g_s[m0 + p];
                    float bv = 3.4e38f; int bi = 0x7fffffff;
                    for (int n = lane; n < N_EMB; n += 32) {
                        const float4* e4 = reinterpret_cast<const float4*>(emb + (size_t)n * K_DIM);
                        float acc = 0.f;
                        #pragma unroll 8
                        for (int k4 = 0; k4 < 64; ++k4) {
                            float4 v = e4[k4];
                            int k = k4 * 4;
                            acc = fmaf(zs[k][p], v.x, acc);
                            acc = fmaf(zs[k + 1][p], v.y, acc);
                            acc = fmaf(zs[k + 2][p], v.z, acc);
                            acc = fmaf(zs[k + 3][p], v.w, acc);
                        }
                        float dd = fmaf(-2.f, acc, s + g_t[n]);
                        if (dd < bv || (dd == bv && n < bi)) { bv = dd; bi = n; }
                    }
                    #pragma unroll
                    for (int o = 16; o; o >>= 1) {
                        float ov = __shfl_xor_sync(0xffffffffu, bv, o);
                        int   oi = __shfl_xor_sync(0xffffffffu, bi, o);
                        if (ov < bv || (ov == bv && oi < bi)) { bv = ov; bi = oi; }
                    }
                    if (lane == 0)
                        atomicMin(&keys[p], ((u64)fkey(bv) << 32) | (unsigned)bi);
                }
            }
        }
    }
    __syncthreads();
    if (tid < 32) {
        int bi = (int)(keys[tid] & 0xFFFFFFFFu);
        sidx[tid] = bi;
        out[(size_t)Z_ELEMS + 1 + m0 + tid] = (float)bi;
    }
    __syncthreads();

    for (int i = tid; i < 32 * 256; i += 256) {
        int r = i >> 8, c = i & 255;
        sm[r][c] = emb[(size_t)sidx[r] * K_DIM + c];
    }
    __syncthreads();
    float part = 0.f;
    #pragma unroll
    for (int it = 0; it < 8; ++it) {                 // float4 global writes
        int f = it * 256 + tid;
        int c = f >> 3, r4 = (f & 7) * 4;
        size_t o = ((size_t)b * K_DIM + c) * HW + hw0 + r4;
        float4 v = make_float4(sm[r4][c], sm[r4 + 1][c], sm[r4 + 2][c], sm[r4 + 3][c]);
        *reinterpret_cast<float4*>(&out[o]) = v;
        float d0 = v.x - zs[c][r4];
        float d1 = v.y - zs[c][r4 + 1];
        float d2 = v.z - zs[c][r4 + 2];
        float d3 = v.w - zs[c][r4 + 3];
        part = fmaf(d0, d0, part);
        part = fmaf(d1, d1, part);
        part = fmaf(d2, d2, part);
        part = fmaf(d3, d3, part);
    }
    red[tid] = part;
    __syncthreads();
    for (int st = 128; st > 0; st >>= 1) {
        if (tid < st) red[tid] += red[tid + st];
        __syncthreads();
    }
    if (tid == 0) g_part[blockIdx.x] = red[0];
}

// ===================== kernel E: final loss ==============================
__global__ void k_loss(float* __restrict__ out) {
    __shared__ double red[256];
    const int tid = threadIdx.x;
    double s = 0.0;
    for (int i = tid; i < GATHER_BLOCKS; i += 256) s += (double)g_part[i];
    red[tid] = s;
    __syncthreads();
    for (int k = 128; k > 0; k >>= 1) {
        if (tid < k) red[tid] += red[tid + k];
        __syncthreads();
    }
    if (tid == 0) out[Z_ELEMS] = (float)(red[0] / (double)Z_ELEMS);
}

// =========================================================================
extern "C" void kernel_launch(void* const* d_in, const int* in_sizes, int n_in,
                              void* d_out, int out_size) {
    const float* z;
    const float* emb;
    if (n_in >= 2 && in_sizes[0] == N_EMB * K_DIM && in_sizes[1] == Z_ELEMS) {
        emb = (const float*)d_in[0];
        z   = (const float*)d_in[1];
    } else {
        z   = (const float*)d_in[0];
        emb = (const float*)d_in[1];
    }
    float* out = (float*)d_out;

    static bool attr_set = false;
    if (!attr_set) {
        cudaFuncSetAttribute(k_gemm, cudaFuncAttributeMaxDynamicSharedMemorySize, 112640);
        cudaFuncSetAttribute(k_select, cudaFuncAttributeMaxDynamicSharedMemorySize, 67840);
        attr_set = true;
    }

    // embnorm launched twice (idempotent) so ncu's capture index 3 = k_gemm
    k_split<<<4100, 256>>>(z, emb);
    k_embnorm<<<4, 256>>>(emb);
    k_embnorm<<<4, 256>>>(emb);
    k_gemm<<<2048, 256, 112640>>>();
    k_select<<<M_TOT / 32, 256, 67840>>>(z, emb, out);
    k_loss<<<1, 256>>>(out);
}

// round 15
// speedup vs baseline: 1.1203x; 1.1203x over previous
#include <cuda_runtime.h>
#include <cuda_bf16.h>
#include <cuda_fp16.h>
#include <cstdint>

#define M_TOT   131072
#define N_EMB   1024
#define K_DIM   256
#define HW      4096
#define Z_ELEMS 33554432
#define GATHER_BLOCKS 4096
#define WINF    2.5e-3f
#define WSEL    3.0e-3f

typedef unsigned long long u64;

__device__ float g_t[N_EMB];
__device__ float g_s[M_TOT];
__device__ float g_part[GATHER_BLOCKS];
__device__ __nv_bfloat16 g_A[(size_t)M_TOT * K_DIM];   // bf16(z), [m][k]
__device__ __nv_bfloat16 g_B[(size_t)N_EMB * K_DIM];   // bf16(emb), [n][k]
// per pixel 32 uints: half0 [cnt, e1..e15] @0, half1 [cnt, e1..e15] @16
// entry = (fp16(u) << 16) | n
__device__ unsigned g_candu[(size_t)M_TOT * 32];

#define SW128(o) ((o) ^ (((o) >> 3) & 0x70))

__device__ __forceinline__ uint32_t smem_u32(const void* p) {
    uint32_t a;
    asm("{ .reg .u64 t; cvta.to.shared.u64 t, %1; cvt.u32.u64 %0, t; }" : "=r"(a) : "l"(p));
    return a;
}
__device__ __forceinline__ unsigned fkey(float f) {
    unsigned b = __float_as_uint(f);
    return (b & 0x80000000u) ? ~b : (b | 0x80000000u);
}
__device__ __forceinline__ float fdecode(unsigned k) {
    unsigned b = (k & 0x80000000u) ? (k ^ 0x80000000u) : ~k;
    return __uint_as_float(b);
}

#define LDSM_X4(r0, r1, r2, r3, addr) \
    asm volatile("ldmatrix.sync.aligned.m8n8.x4.shared.b16 {%0,%1,%2,%3}, [%4];" \
        : "=r"(r0), "=r"(r1), "=r"(r2), "=r"(r3) : "r"(addr))

#define MMA16816(d, a, b0, b1) \
    asm volatile("mma.sync.aligned.m16n8k16.row.col.f32.bf16.bf16.f32 " \
        "{%0,%1,%2,%3}, {%4,%5,%6,%7}, {%8,%9}, {%0,%1,%2,%3};" \
        : "+f"((d)[0]), "+f"((d)[1]), "+f"((d)[2]), "+f"((d)[3]) \
        : "r"((a)[0]), "r"((a)[1]), "r"((a)[2]), "r"((a)[3]), "r"(b0), "r"(b1))

#define CP_ASYNC16(dst, src) \
    asm volatile("cp.async.cg.shared.global [%0], [%1], 16;" :: "r"(dst), "l"(src))
#define CP_COMMIT() asm volatile("cp.async.commit_group;")
#define CP_WAIT0()  asm volatile("cp.async.wait_group 0;")

// ===================== kernel A: fused split (z + emb -> bf16) ===========
__global__ __launch_bounds__(256) void k_split(const float* __restrict__ z,
                                               const float* __restrict__ emb) {
    const int tid = threadIdx.x;
    if (blockIdx.x >= 4096) {
        int n = (blockIdx.x - 4096) * 256 + tid;
        const float4* er = reinterpret_cast<const float4*>(emb + (size_t)n * K_DIM);
        #pragma unroll 4
        for (int c8 = 0; c8 < 32; ++c8) {
            float4 v0 = er[c8 * 2], v1 = er[c8 * 2 + 1];
            __nv_bfloat16 h[8] = {
                __float2bfloat16_rn(v0.x), __float2bfloat16_rn(v0.y),
                __float2bfloat16_rn(v0.z), __float2bfloat16_rn(v0.w),
                __float2bfloat16_rn(v1.x), __float2bfloat16_rn(v1.y),
                __float2bfloat16_rn(v1.z), __float2bfloat16_rn(v1.w) };
            *reinterpret_cast<uint4*>(&g_B[(size_t)n * K_DIM + c8 * 8]) =
                *reinterpret_cast<uint4*>(h);
        }
        return;
    }
    __shared__ float zs[256][33];
    const int m0 = blockIdx.x * 32, b = m0 / HW, hw0 = m0 & (HW - 1);
    #pragma unroll
    for (int it = 0; it < 8; ++it) {
        int f = it * 256 + tid;
        int c = f >> 3, r4 = (f & 7) * 4;
        float4 v = *reinterpret_cast<const float4*>(
            z + ((size_t)b * K_DIM + c) * HW + hw0 + r4);
        zs[c][r4] = v.x; zs[c][r4 + 1] = v.y;
        zs[c][r4 + 2] = v.z; zs[c][r4 + 3] = v.w;
    }
    __syncthreads();
    for (int i = tid; i < 1024; i += 256) {
        int r = i >> 5, c8 = (i & 31) * 8;
        __nv_bfloat16 h[8];
        #pragma unroll
        for (int j = 0; j < 8; ++j) h[j] = __float2bfloat16_rn(zs[c8 + j][r]);
        *reinterpret_cast<uint4*>(&g_A[(size_t)(m0 + r) * K_DIM + c8]) =
            *reinterpret_cast<uint4*>(h);
    }
    if (tid < 32) {
        float s = 0.f;
        #pragma unroll 8
        for (int c = 0; c < K_DIM; ++c) { float v = zs[c][tid]; s = fmaf(v, v, s); }
        g_s[m0 + tid] = s;
    }
}

// ===================== kernel B: emb norms (sequential-k, exact) =========
__global__ void k_embnorm(const float* __restrict__ emb) {
    int n = blockIdx.x * blockDim.x + threadIdx.x;
    if (n < N_EMB) {
        const float* e = emb + (size_t)n * K_DIM;
        float s = 0.f;
        #pragma unroll 8
        for (int c = 0; c < K_DIM; ++c) s = fmaf(e[c], e[c], s);
        g_t[n] = s;
    }
}

// ===================== kernel C: fused GEMM + candidate lists ============
// Grid 2048 = 1024 m-tiles x 2 n-halves. Warp grid 4(m)x2(n), tile 32x64.
// Candidates appended to per-row smem lists WITH fp16(u): select prunes
// globally before rescoring. Threshold = global-so-far row min + WINF.
// smem: A 65536 | B 32768 | Ts 4096 | tminU 512 | lists 7680 | cnts 512
__global__ __launch_bounds__(256, 2) void k_gemm() {
    extern __shared__ __align__(16) unsigned char smem[];
    const uint32_t sbase = smem_u32(smem);
    const uint32_t SA = 0, SB = 65536, STS = 98304, STM = 102400,
                   SLI = 102912, SCN = 110592;   // total 111104
    float*    Ts    = reinterpret_cast<float*>(smem + STS);
    unsigned* tminU = reinterpret_cast<unsigned*>(smem + STM);   // 128
    unsigned* lists = reinterpret_cast<unsigned*>(smem + SLI);   // 128*15
    int*      cnts  = reinterpret_cast<int*>(smem + SCN);        // 128

    const int tid = threadIdx.x, wid = tid >> 5, lane = tid & 31;
    const int m0 = (blockIdx.x >> 1) * 128;
    const int half = blockIdx.x & 1;
    const int nbase = half * 512;
    const int mw = wid >> 1, nw = wid & 1;
    const int g = lane >> 2, t = lane & 3;
    const int li = lane & 7, ls = lane >> 3;

    const unsigned char* gAb = reinterpret_cast<const unsigned char*>(g_A);
    const unsigned char* gBb = reinterpret_cast<const unsigned char*>(g_B);
    const int r  = tid >> 3;
    const int cb = (tid & 7) * 16;

    for (int i = tid; i < N_EMB; i += 256) Ts[i] = g_t[i];
    if (tid < 128) { tminU[tid] = 0xFFFFFFFFu; cnts[tid] = 0; }

    #pragma unroll
    for (int kc = 0; kc < 4; ++kc)
        #pragma unroll
        for (int i = 0; i < 4; ++i) {
            int f = tid + i * 256;
            int rr = f >> 3, cc = (f & 7) * 16;
            CP_ASYNC16(sbase + SA + kc * 16384u + SW128(rr * 128 + cc),
                       gAb + (size_t)(m0 + rr) * 512 + kc * 128 + cc);
        }
    #pragma unroll
    for (int i = 0; i < 4; ++i) {
        int rr = r + i * 32;
        CP_ASYNC16(sbase + SB + SW128(rr * 128 + cb),
                   gBb + (size_t)(nbase + rr) * 512 + cb);
    }
    CP_COMMIT();

    float d[2][8][4];
    #pragma unroll
    for (int i = 0; i < 2; ++i)
        #pragma unroll
        for (int j = 0; j < 8; ++j)
            #pragma unroll
            for (int q = 0; q < 4; ++q) d[i][j][q] = 0.f;

    uint32_t buf = 0;
    for (int nc = 0; nc < 4; ++nc) {
        for (int kc = 0; kc < 4; ++kc) {
            CP_WAIT0();
            __syncthreads();
            int nn = nc, nk = kc + 1;
            if (nk == 4) { nk = 0; ++nn; }
            if (nn < 4) {
                uint32_t nb = buf ^ 1;
                #pragma unroll
                for (int i = 0; i < 4; ++i) {
                    int rr = r + i * 32;
                    CP_ASYNC16(sbase + SB + nb * 16384u + SW128(rr * 128 + cb),
                               gBb + (size_t)(nbase + nn * 128 + rr) * 512 + nk * 128 + cb);
                }
                CP_COMMIT();
            }
            const uint32_t sAu = sbase + SA + kc * 16384u;
            const uint32_t sBu = sbase + SB + buf * 16384u;
            #pragma unroll
            for (int ks = 0; ks < 4; ++ks) {
                uint32_t a[2][4];
                #pragma unroll
                for (int mb = 0; mb < 2; ++mb) {
                    int row = mw * 32 + mb * 16 + li + (ls & 1) * 8;
                    int boff = ks * 32 + (ls >> 1) * 16;
                    LDSM_X4(a[mb][0], a[mb][1], a[mb][2], a[mb][3],
                            sAu + SW128(row * 128 + boff));
                }
                #pragma unroll
                for (int nbp = 0; nbp < 4; ++nbp) {
                    uint32_t bf[4];
                    int row = nw * 64 + nbp * 16 + li + (ls >> 1) * 8;
                    int boff = ks * 32 + (ls & 1) * 16;
                    LDSM_X4(bf[0], bf[1], bf[2], bf[3],
                            sBu + SW128(row * 128 + boff));
                    #pragma unroll
                    for (int mb = 0; mb < 2; ++mb) {
                        MMA16816(d[mb][nbp * 2],     a[mb], bf[0], bf[1]);
                        MMA16816(d[mb][nbp * 2 + 1], a[mb], bf[2], bf[3]);
                    }
                }
            }
            buf ^= 1;
        }
        // ---- epilogue: u-transform, row-min, list append ----
        float rowmin[4];
        #pragma unroll
        for (int mb = 0; mb < 2; ++mb) {
            float mn0 = 3.4e38f, mn1 = 3.4e38f;
            #pragma unroll
            for (int nb = 0; nb < 8; ++nb) {
                int cg = nbase + nc * 128 + nw * 64 + nb * 8 + t * 2;
                float t0 = Ts[cg], t1 = Ts[cg + 1];
                float u0 = fmaf(-2.f, d[mb][nb][0], t0);
                float u1 = fmaf(-2.f, d[mb][nb][1], t1);
                float u2 = fmaf(-2.f, d[mb][nb][2], t0);
                float u3 = fmaf(-2.f, d[mb][nb][3], t1);
                d[mb][nb][0] = u0; d[mb][nb][1] = u1;
                d[mb][nb][2] = u2; d[mb][nb][3] = u3;
                mn0 = fminf(mn0, fminf(u0, u1));
                mn1 = fminf(mn1, fminf(u2, u3));
            }
            rowmin[mb * 2] = mn0; rowmin[mb * 2 + 1] = mn1;
        }
        #pragma unroll
        for (int j = 0; j < 4; ++j) {
            rowmin[j] = fminf(rowmin[j], __shfl_xor_sync(0xffffffffu, rowmin[j], 1));
            rowmin[j] = fminf(rowmin[j], __shfl_xor_sync(0xffffffffu, rowmin[j], 2));
        }
        unsigned tk[4];
        #pragma unroll
        for (int j = 0; j < 4; ++j) tk[j] = fkey(rowmin[j]);
        if (t == 0) {
            #pragma unroll
            for (int j = 0; j < 4; ++j) {
                int row = mw * 32 + (j >> 1) * 16 + (j & 1) * 8 + g;
                unsigned old = atomicMin(&tminU[row], tk[j]);
                tk[j] = (old < tk[j]) ? old : tk[j];
            }
        }
        #pragma unroll
        for (int j = 0; j < 4; ++j)
            tk[j] = __shfl_sync(0xffffffffu, tk[j], lane & ~3);
        #pragma unroll
        for (int mb = 0; mb < 2; ++mb) {
            #pragma unroll
            for (int h = 0; h < 2; ++h) {
                int row = mw * 32 + mb * 16 + h * 8 + g;
                float thr = fdecode(tk[mb * 2 + h]) + WINF;
                #pragma unroll
                for (int nb = 0; nb < 8; ++nb) {
                    int col = nbase + nc * 128 + nw * 64 + nb * 8 + t * 2;
                    float u0 = d[mb][nb][h * 2];
                    float u1 = d[mb][nb][h * 2 + 1];
                    if (u0 < thr) {
                        unsigned e = ((unsigned)__half_as_ushort(__float2half_rn(u0)) << 16)
                                     | (unsigned)col;
                        int idx = atomicAdd(&cnts[row], 1);
                        if (idx < 15) lists[row * 15 + idx] = e;
                    }
                    if (u1 < thr) {
                        unsigned e = ((unsigned)__half_as_ushort(__float2half_rn(u1)) << 16)
                                     | (unsigned)(col + 1);
                        int idx = atomicAdd(&cnts[row], 1);
                        if (idx < 15) lists[row * 15 + idx] = e;
                    }
                }
            }
        }
        #pragma unroll
        for (int i = 0; i < 2; ++i)
            #pragma unroll
            for (int j = 0; j < 8; ++j)
                #pragma unroll
                for (int q = 0; q < 4; ++q) d[i][j][q] = 0.f;
    }
    __syncthreads();

    // ---- end phase: dump lists ----
    if (tid < 128) {
        int row = tid, m = m0 + row;
        int cnt = cnts[row];
        unsigned* cd = g_candu + (size_t)m * 32 + half * 16;
        cd[0] = (unsigned)cnt;
        int lim = cnt < 15 ? cnt : 15;
        for (int j = 0; j < lim; ++j) cd[1 + j] = lists[row * 15 + j];
    }
}

// ===================== kernel D: prune + rescore + gather + loss =========
__global__ __launch_bounds__(256) void k_select(const float* __restrict__ z,
                                                const float* __restrict__ emb,
                                                float* __restrict__ out) {
    extern __shared__ __align__(16) unsigned char dsm[];
    float (*zs)[33]  = reinterpret_cast<float(*)[33]>(dsm);             // 33792
    unsigned* pairs  = reinterpret_cast<unsigned*>(dsm + 33792);        // 4096 (phase1)
    int*      pcnt   = reinterpret_cast<int*>(dsm + 37888);             // 4
    unsigned* ovfm   = reinterpret_cast<unsigned*>(dsm + 37892);        // 4
    float (*sm)[257] = reinterpret_cast<float(*)[257]>(dsm + 33792);    // 32896 (phase2)
    u64*   keys      = reinterpret_cast<u64*>(dsm + 66688);             // 256
    int*   sidx      = reinterpret_cast<int*>(dsm + 66944);             // 128
    float* red       = reinterpret_cast<float*>(dsm + 67072);           // 1024 -> 68096

    const int tid = threadIdx.x, wid = tid >> 5, lane = tid & 31;
    const int m0 = blockIdx.x * 32, b = m0 / HW, hw0 = m0 & (HW - 1);

    if (tid == 0) { *pcnt = 0; *ovfm = 0u; }
    if (tid < 32) keys[tid] = ~0ull;
    #pragma unroll
    for (int it = 0; it < 8; ++it) {
        int f = it * 256 + tid;
        int c = f >> 3, r4 = (f & 7) * 4;
        float4 v = *reinterpret_cast<const float4*>(
            z + ((size_t)b * K_DIM + c) * HW + hw0 + r4);
        zs[c][r4] = v.x; zs[c][r4 + 1] = v.y;
        zs[c][r4 + 2] = v.z; zs[c][r4 + 3] = v.w;
    }
    __syncthreads();

    // phase 1: load 32 entries/pixel (8 threads x uint4), global min, filter
    {
        const int p = tid >> 3, g8 = tid & 7;       // pixel, slot group
        uint4 ev = *reinterpret_cast<const uint4*>(
            &g_candu[(size_t)(m0 + p) * 32 + g8 * 4]);
        unsigned base = lane & ~7u;
        unsigned cnt0 = __shfl_sync(0xffffffffu, ev.x, base);
        unsigned cnt1 = __shfl_sync(0xffffffffu, ev.x, base + 4);
        bool ovf = (cnt0 > 15u) || (cnt1 > 15u);
        unsigned en[4] = {ev.x, ev.y, ev.z, ev.w};
        float uv[4];
        bool val[4];
        #pragma unroll
        for (int j = 0; j < 4; ++j) {
            int s = g8 * 4 + j;
            bool v0 = (s >= 1 && s <= 15 && (unsigned)s <= cnt0);
            bool v1 = (s >= 17 && (unsigned)(s - 16) <= cnt1);
            val[j] = v0 || v1;
            uv[j] = val[j] ? __half2float(__ushort_as_half((unsigned short)(en[j] >> 16)))
                           : 3.4e38f;
        }
        float mn = fminf(fminf(uv[0], uv[1]), fminf(uv[2], uv[3]));
        #pragma unroll
        for (int o = 1; o < 8; o <<= 1)
            mn = fminf(mn, __shfl_xor_sync(0xffffffffu, mn, o));
        if (ovf) {
            if (g8 == 0) atomicOr(ovfm, 1u << p);
        } else {
            float thr = mn + WSEL;
            #pragma unroll
            for (int j = 0; j < 4; ++j) {
                if (val[j] && uv[j] <= thr) {
                    int idx = atomicAdd(pcnt, 1);
                    pairs[idx] = ((unsigned)p << 16) | (en[j] & 0xFFFFu);
                }
            }
        }
    }
    __syncthreads();

    const int T = *pcnt;
    for (int i = tid; i < T; i += 256) {
        unsigned pr = pairs[i];
        int p = pr >> 16, n = pr & 0xFFFF;
        const float4* e4 = reinterpret_cast<const float4*>(emb + (size_t)n * K_DIM);
        float acc = 0.f;
        #pragma unroll 8
        for (int k4 = 0; k4 < 64; ++k4) {
            float4 v = e4[k4];
            int k = k4 * 4;
            acc = fmaf(zs[k][p], v.x, acc);
            acc = fmaf(zs[k + 1][p], v.y, acc);
            acc = fmaf(zs[k + 2][p], v.z, acc);
            acc = fmaf(zs[k + 3][p], v.w, acc);
        }
        float dd = fmaf(-2.f, acc, g_s[m0 + p] + g_t[n]);
        atomicMin(&keys[p], ((u64)fkey(dd) << 32) | (unsigned)n);
    }
    {
        unsigned obal = *ovfm;
        if (obal) {
            for (int p = wid; p < 32; p += 8) {
                if ((obal >> p) & 1u) {
                    const float s = g_s[m0 + p];
                    float bv = 3.4e38f; int bi = 0x7fffffff;
                    for (int n = lane; n < N_EMB; n += 32) {
                        const float4* e4 = reinterpret_cast<const float4*>(emb + (size_t)n * K_DIM);
                        float acc = 0.f;
                        #pragma unroll 8
                        for (int k4 = 0; k4 < 64; ++k4) {
                            float4 v = e4[k4];
                            int k = k4 * 4;
                            acc = fmaf(zs[k][p], v.x, acc);
                            acc = fmaf(zs[k + 1][p], v.y, acc);
                            acc = fmaf(zs[k + 2][p], v.z, acc);
                            acc = fmaf(zs[k + 3][p], v.w, acc);
                        }
                        float dd = fmaf(-2.f, acc, s + g_t[n]);
                        if (dd < bv || (dd == bv && n < bi)) { bv = dd; bi = n; }
                    }
                    #pragma unroll
                    for (int o = 16; o; o >>= 1) {
                        float ov = __shfl_xor_sync(0xffffffffu, bv, o);
                        int   oi = __shfl_xor_sync(0xffffffffu, bi, o);
                        if (ov < bv || (ov == bv && oi < bi)) { bv = ov; bi = oi; }
                    }
                    if (lane == 0)
                        atomicMin(&keys[p], ((u64)fkey(bv) << 32) | (unsigned)bi);
                }
            }
        }
    }
    __syncthreads();
    if (tid < 32) {
        int bi = (int)(keys[tid] & 0xFFFFFFFFu);
        sidx[tid] = bi;
        out[(size_t)Z_ELEMS + 1 + m0 + tid] = (float)bi;
    }
    __syncthreads();

    for (int i = tid; i < 32 * 256; i += 256) {
        int r = i >> 8, c = i & 255;
        sm[r][c] = emb[(size_t)sidx[r] * K_DIM + c];
    }
    __syncthreads();
    float part = 0.f;
    #pragma unroll
    for (int it = 0; it < 8; ++it) {
        int f = it * 256 + tid;
        int c = f >> 3, r4 = (f & 7) * 4;
        size_t o = ((size_t)b * K_DIM + c) * HW + hw0 + r4;
        float4 v = make_float4(sm[r4][c], sm[r4 + 1][c], sm[r4 + 2][c], sm[r4 + 3][c]);
        *reinterpret_cast<float4*>(&out[o]) = v;
        float d0 = v.x - zs[c][r4];
        float d1 = v.y - zs[c][r4 + 1];
        float d2 = v.z - zs[c][r4 + 2];
        float d3 = v.w - zs[c][r4 + 3];
        part = fmaf(d0, d0, part);
        part = fmaf(d1, d1, part);
        part = fmaf(d2, d2, part);
        part = fmaf(d3, d3, part);
    }
    red[tid] = part;
    __syncthreads();
    for (int st = 128; st > 0; st >>= 1) {
        if (tid < st) red[tid] += red[tid + st];
        __syncthreads();
    }
    if (tid == 0) g_part[blockIdx.x] = red[0];
}

// ===================== kernel E: final loss ==============================
__global__ void k_loss(float* __restrict__ out) {
    __shared__ double red[256];
    const int tid = threadIdx.x;
    double s = 0.0;
    for (int i = tid; i < GATHER_BLOCKS; i += 256) s += (double)g_part[i];
    red[tid] = s;
    __syncthreads();
    for (int k = 128; k > 0; k >>= 1) {
        if (tid < k) red[tid] += red[tid + k];
        __syncthreads();
    }
    if (tid == 0) out[Z_ELEMS] = (float)(red[0] / (double)Z_ELEMS);
}

// =========================================================================
extern "C" void kernel_launch(void* const* d_in, const int* in_sizes, int n_in,
                              void* d_out, int out_size) {
    const float* z;
    const float* emb;
    if (n_in >= 2 && in_sizes[0] == N_EMB * K_DIM && in_sizes[1] == Z_ELEMS) {
        emb = (const float*)d_in[0];
        z   = (const float*)d_in[1];
    } else {
        z   = (const float*)d_in[0];
        emb = (const float*)d_in[1];
    }
    float* out = (float*)d_out;

    static bool attr_set = false;
    if (!attr_set) {
        cudaFuncSetAttribute(k_gemm, cudaFuncAttributeMaxDynamicSharedMemorySize, 111104);
        cudaFuncSetAttribute(k_select, cudaFuncAttributeMaxDynamicSharedMemorySize, 68096);
        attr_set = true;
    }

    // ncu captures launch index 3 -> k_select profiled this round
    k_split<<<4100, 256>>>(z, emb);
    k_embnorm<<<4, 256>>>(emb);
    k_gemm<<<2048, 256, 111104>>>();
    k_select<<<M_TOT / 32, 256, 68096>>>(z, emb, out);
    k_loss<<<1, 256>>>(out);
}